// round 2
// baseline (speedup 1.0000x reference)
#include <cuda_runtime.h>
#include <math_constants.h>

// Outputs packed float32, reference return order:
//   [0,    N)   t_hit
//   [N,   2N)   sphere_idx (as float, -1 for miss)
//   [2N,  5N)   hit_points  (N,3)
//   [5N,  8N)   hit_normals (N,3)
//
// Correctness strategy: replicate the reference's float32 operation sequence
// exactly (separately-rounded mul/add for elementwise ops, FMA-chain for the
// matmul dots, IEEE sqrt/div) so that hit/miss and argmin decisions match.
// Performance strategy: all roots for one ray share denominator 2a>0, so
// ordering of t == ordering of numerators; divisions only on improvement.
// disc<0 (definite miss, identical in reference) skips the sqrt tail.

#define MAX_SPH 256
#define BLOCK   256

__global__ __launch_bounds__(BLOCK)
void raysphere_kernel(const float* __restrict__ ro,
                      const float* __restrict__ rd,
                      const float* __restrict__ sc,
                      const float* __restrict__ sr,
                      float* __restrict__ out,
                      int n_rays, int n_sph)
{
    __shared__ float4 s_sph[MAX_SPH];

    const int tid = threadIdx.x;

    // (cx, cy, cz, |c|^2 - r^2), rounded exactly like the reference:
    // squares rounded, left-to-right sum, then subtract r*r.
    for (int j = tid; j < n_sph; j += BLOCK) {
        float cx = sc[3 * j + 0];
        float cy = sc[3 * j + 1];
        float cz = sc[3 * j + 2];
        float r  = sr[j];
        float s2 = __fadd_rn(__fadd_rn(__fmul_rn(cx, cx), __fmul_rn(cy, cy)),
                             __fmul_rn(cz, cz));
        float cconst = __fsub_rn(s2, __fmul_rn(r, r));
        s_sph[j] = make_float4(cx, cy, cz, cconst);
    }
    __syncthreads();

    const int i = blockIdx.x * BLOCK + tid;
    if (i >= n_rays) return;

    const float ox = ro[3 * i + 0];
    const float oy = ro[3 * i + 1];
    const float oz = ro[3 * i + 2];
    const float dx = rd[3 * i + 0];
    const float dy = rd[3 * i + 1];
    const float dz = rd[3 * i + 2];

    // jnp.sum(d*d): rounded squares, left-to-right add
    const float a   = __fadd_rn(__fadd_rn(__fmul_rn(dx, dx), __fmul_rn(dy, dy)),
                                __fmul_rn(dz, dz));
    const float ddo = __fadd_rn(__fadd_rn(__fmul_rn(dx, ox), __fmul_rn(dy, oy)),
                                __fmul_rn(dz, oz));
    const float on2 = __fadd_rn(__fadd_rn(__fmul_rn(ox, ox), __fmul_rn(oy, oy)),
                                __fmul_rn(oz, oz));
    const float fa4   = __fmul_rn(4.0f, a);   // (4.0 * a), then * c per sphere
    const float two_a = __fmul_rn(2.0f, a);

    float best_num = CUDART_INF_F;   // numerator-domain reject bound
    float best_t   = CUDART_INF_F;   // reference-exact t value
    int   best_j   = 0;

    #pragma unroll 4
    for (int j = 0; j < n_sph; j++) {
        const float4 s = s_sph[j];

        // matmul dots: fma chain, k = 0 -> 2 (GEMM accumulation order)
        const float ddc = __fmaf_rn(dz, s.z, __fmaf_rn(dy, s.y, __fmul_rn(dx, s.x)));
        const float odc = __fmaf_rn(oz, s.z, __fmaf_rn(oy, s.y, __fmul_rn(ox, s.x)));

        const float b = __fmul_rn(2.0f, __fsub_rn(ddo, ddc));
        const float c = __fadd_rn(__fsub_rn(on2, __fmul_rn(2.0f, odc)), s.w);
        const float disc = __fsub_rn(__fmul_rn(b, b), __fmul_rn(fa4, c));

        if (disc >= 0.0f) {                       // miss => invalid in ref too
            const float sq   = __fsqrt_rn(disc);  // = sqrt(max(disc,0)) here
            const float negb = -b;
            const float num1 = __fsub_rn(negb, sq);
            const float num2 = __fadd_rn(negb, sq);
            // sign(t1) == sign(num1) since 2a > 0; pick near root if positive
            const float num = (num1 > 0.0f) ? num1 : num2;
            // valid = (disc>=0) & (t>0); t>0 <=> num>0 (positive denominator)
            if (num > 0.0f && num < best_num) {
                best_num = num;
                const float t = __fdiv_rn(num, two_a);   // reference-exact t
                if (t < best_t) { best_t = t; best_j = j; }  // first-min tie-break
            }
        }
    }

    const float t_hit = best_t;
    const bool  any   = isfinite(t_hit);

    const long long N = n_rays;
    out[i]     = t_hit;
    out[N + i] = any ? (float)best_j : -1.0f;

    // hit_points = o + t*d (mul then add, no fma — matches reference)
    const float hx = __fadd_rn(ox, __fmul_rn(t_hit, dx));
    const float hy = __fadd_rn(oy, __fmul_rn(t_hit, dy));
    const float hz = __fadd_rn(oz, __fmul_rn(t_hit, dz));
    out[2 * N + 3 * i + 0] = hx;
    out[2 * N + 3 * i + 1] = hy;
    out[2 * N + 3 * i + 2] = hz;

    const float4 cb = s_sph[any ? best_j : 0];
    const float nx = __fsub_rn(hx, cb.x);
    const float ny = __fsub_rn(hy, cb.y);
    const float nz = __fsub_rn(hz, cb.z);
    const float nn = __fadd_rn(__fadd_rn(__fmul_rn(nx, nx), __fmul_rn(ny, ny)),
                               __fmul_rn(nz, nz));
    const float len = __fsqrt_rn(nn);
    out[5 * N + 3 * i + 0] = any ? __fdiv_rn(nx, len) : 0.0f;
    out[5 * N + 3 * i + 1] = any ? __fdiv_rn(ny, len) : 0.0f;
    out[5 * N + 3 * i + 2] = any ? __fdiv_rn(nz, len) : 0.0f;
}

extern "C" void kernel_launch(void* const* d_in, const int* in_sizes, int n_in,
                              void* d_out, int out_size)
{
    const float* ro = (const float*)d_in[0];   // (N,3)
    const float* rd = (const float*)d_in[1];   // (N,3)
    const float* sc = (const float*)d_in[2];   // (M,3)
    const float* sr = (const float*)d_in[3];   // (M,)

    const int n_rays = in_sizes[0] / 3;
    const int n_sph  = in_sizes[3];

    float* out = (float*)d_out;

    const int grid = (n_rays + BLOCK - 1) / BLOCK;
    raysphere_kernel<<<grid, BLOCK>>>(ro, rd, sc, sr, out, n_rays, n_sph);
}

// round 3
// speedup vs baseline: 1.1949x; 1.1949x over previous
#include <cuda_runtime.h>
#include <math_constants.h>

// Outputs packed float32, reference return order:
//   [0,    N)   t_hit
//   [N,   2N)   sphere_idx (as float, -1 for miss)
//   [2N,  5N)   hit_points  (N,3)
//   [5N,  8N)   hit_normals (N,3)
//
// Bit-exact replication of the reference fp32 op sequence for all decision
// quantities, evaluated in the half-b domain (all scalings are powers of two,
// which commute exactly with IEEE rn rounding, sqrt and div).
// Inner loop processes 2 spheres per lane via packed f32x2 ops (2 fp32 FMAs
// per issue slot) — the binding resource is fp32 issue bandwidth.

#define MAX_SPH  256
#define MAX_PAIR (MAX_SPH / 2)
#define BLOCK    256

typedef unsigned long long u64;

__device__ __forceinline__ u64 pk2(float lo, float hi) {
    u64 r; asm("mov.b64 %0, {%1, %2};" : "=l"(r) : "f"(lo), "f"(hi)); return r;
}
__device__ __forceinline__ void upk2(float& lo, float& hi, u64 v) {
    asm("mov.b64 {%0, %1}, %2;" : "=f"(lo), "=f"(hi) : "l"(v));
}
__device__ __forceinline__ u64 mul2(u64 a, u64 b) {
    u64 d; asm("mul.rn.f32x2 %0, %1, %2;" : "=l"(d) : "l"(a), "l"(b)); return d;
}
__device__ __forceinline__ u64 add2(u64 a, u64 b) {
    u64 d; asm("add.rn.f32x2 %0, %1, %2;" : "=l"(d) : "l"(a), "l"(b)); return d;
}
__device__ __forceinline__ u64 fma2(u64 a, u64 b, u64 c) {
    u64 d; asm("fma.rn.f32x2 %0, %1, %2, %3;" : "=l"(d) : "l"(a), "l"(b), "l"(c)); return d;
}

__global__ __launch_bounds__(BLOCK)
void raysphere_kernel(const float* __restrict__ ro,
                      const float* __restrict__ rd,
                      const float* __restrict__ sc,
                      const float* __restrict__ sr,
                      float* __restrict__ out,
                      int n_rays, int n_sph)
{
    // Pre-paired sphere data for packed loads:
    //   sA[k] = {x(2k), x(2k+1), y(2k), y(2k+1)}
    //   sB[k] = {z(2k), z(2k+1), w(2k), w(2k+1)},  w = |c|^2 - r^2
    __shared__ float4 sA[MAX_PAIR];
    __shared__ float4 sB[MAX_PAIR];
    __shared__ float4 s_ctr[MAX_SPH];   // plain centers for the normal gather

    const int tid    = threadIdx.x;
    const int n_pair = n_sph >> 1;

    for (int j = tid; j < n_sph; j += BLOCK) {
        float cx = sc[3 * j + 0];
        float cy = sc[3 * j + 1];
        float cz = sc[3 * j + 2];
        float r  = sr[j];
        float s2 = __fadd_rn(__fadd_rn(__fmul_rn(cx, cx), __fmul_rn(cy, cy)),
                             __fmul_rn(cz, cz));
        float w  = __fsub_rn(s2, __fmul_rn(r, r));
        s_ctr[j] = make_float4(cx, cy, cz, w);
    }
    __syncthreads();
    for (int k = tid; k < n_pair; k += BLOCK) {
        float4 p0 = s_ctr[2 * k], p1 = s_ctr[2 * k + 1];
        sA[k] = make_float4(p0.x, p1.x, p0.y, p1.y);
        sB[k] = make_float4(p0.z, p1.z, p0.w, p1.w);
    }
    __syncthreads();

    const int i = blockIdx.x * BLOCK + tid;
    if (i >= n_rays) return;

    const float ox = ro[3 * i + 0];
    const float oy = ro[3 * i + 1];
    const float oz = ro[3 * i + 2];
    const float dx = rd[3 * i + 0];
    const float dy = rd[3 * i + 1];
    const float dz = rd[3 * i + 2];

    // jnp.sum(v*v): rounded squares, left-to-right add (reference order)
    const float a   = __fadd_rn(__fadd_rn(__fmul_rn(dx, dx), __fmul_rn(dy, dy)),
                                __fmul_rn(dz, dz));
    const float ddo = __fadd_rn(__fadd_rn(__fmul_rn(dx, ox), __fmul_rn(dy, oy)),
                                __fmul_rn(dz, oz));
    const float on2 = __fadd_rn(__fadd_rn(__fmul_rn(ox, ox), __fmul_rn(oy, oy)),
                                __fmul_rn(oz, oz));

    // Packed ray constants; dot chains are computed NEGATED (exact sign flips)
    const u64 pndx = pk2(-dx, -dx), pndy = pk2(-dy, -dy), pndz = pk2(-dz, -dz);
    const u64 pnox = pk2(-ox, -ox), pnoy = pk2(-oy, -oy), pnoz = pk2(-oz, -oz);
    const u64 pddo = pk2(ddo, ddo);
    const u64 pon2 = pk2(on2, on2);
    const u64 pna  = pk2(-a, -a);

    float best_m = CUDART_INF_F;   // half-b numerator domain reject bound
    float best_t = CUDART_INF_F;   // reference-exact t
    int   best_j = 0;

    #pragma unroll 4
    for (int k = 0; k < n_pair; k++) {
        const float4 A = sA[k];           // {x0,x1,y0,y1}
        const float4 B = sB[k];           // {z0,z1,w0,w1}
        const u64 psx = pk2(A.x, A.y);
        const u64 psy = pk2(A.z, A.w);
        const u64 psz = pk2(B.x, B.y);
        const u64 psw = pk2(B.z, B.w);

        // -ddc, -odc : exact negations of reference fma chains (k = 0 -> 2)
        const u64 nddc = fma2(pndz, psz, fma2(pndy, psy, mul2(pndx, psx)));
        const u64 nodc = fma2(pnoz, psz, fma2(pnoy, psy, mul2(pnox, psx)));

        const u64 x2  = add2(pddo, nddc);            //  ddo - ddc   (= b/2)
        const u64 m2o = add2(nodc, nodc);            //  -2*odc (exact scaling)
        const u64 c2  = add2(add2(pon2, m2o), psw);  //  (on2 - 2odc) + cconst
        const u64 q2  = add2(mul2(x2, x2), mul2(pna, c2));   // disc/4

        float qlo, qhi;
        upk2(qlo, qhi, q2);
        if (qlo >= 0.0f || qhi >= 0.0f) {            // rare tail
            float xlo, xhi;
            upk2(xlo, xhi, x2);
            if (qlo >= 0.0f) {
                const float sq = __fsqrt_rn(qlo);    // = sqrt_disc/2 exactly
                const float m1 = __fsub_rn(-xlo, sq);
                const float m0 = __fadd_rn(-xlo, sq);
                const float m  = (m1 > 0.0f) ? m1 : m0;
                if (m > 0.0f && m < best_m) {
                    best_m = m;
                    const float t = __fdiv_rn(m, a); // == num/(2a) exactly
                    if (t < best_t) { best_t = t; best_j = 2 * k; }
                }
            }
            if (qhi >= 0.0f) {
                const float sq = __fsqrt_rn(qhi);
                const float m1 = __fsub_rn(-xhi, sq);
                const float m0 = __fadd_rn(-xhi, sq);
                const float m  = (m1 > 0.0f) ? m1 : m0;
                if (m > 0.0f && m < best_m) {
                    best_m = m;
                    const float t = __fdiv_rn(m, a);
                    if (t < best_t) { best_t = t; best_j = 2 * k + 1; }
                }
            }
        }
    }

    // Scalar remainder if n_sph is odd (not hit for 256)
    for (int j = 2 * n_pair; j < n_sph; j++) {
        const float4 s = s_ctr[j];
        const float ddc = __fmaf_rn(dz, s.z, __fmaf_rn(dy, s.y, __fmul_rn(dx, s.x)));
        const float odc = __fmaf_rn(oz, s.z, __fmaf_rn(oy, s.y, __fmul_rn(ox, s.x)));
        const float x   = __fsub_rn(ddo, ddc);
        const float c   = __fadd_rn(__fsub_rn(on2, __fmul_rn(2.0f, odc)), s.w);
        const float q   = __fsub_rn(__fmul_rn(x, x), __fmul_rn(a, c));
        if (q >= 0.0f) {
            const float sq = __fsqrt_rn(q);
            const float m1 = __fsub_rn(-x, sq);
            const float m0 = __fadd_rn(-x, sq);
            const float m  = (m1 > 0.0f) ? m1 : m0;
            if (m > 0.0f && m < best_m) {
                best_m = m;
                const float t = __fdiv_rn(m, a);
                if (t < best_t) { best_t = t; best_j = j; }
            }
        }
    }

    const float t_hit = best_t;
    const bool  any   = isfinite(t_hit);

    const long long N = n_rays;
    out[i]     = t_hit;
    out[N + i] = any ? (float)best_j : -1.0f;

    // hit_points = o + t*d (mul then add — matches reference)
    const float hx = __fadd_rn(ox, __fmul_rn(t_hit, dx));
    const float hy = __fadd_rn(oy, __fmul_rn(t_hit, dy));
    const float hz = __fadd_rn(oz, __fmul_rn(t_hit, dz));
    out[2 * N + 3 * i + 0] = hx;
    out[2 * N + 3 * i + 1] = hy;
    out[2 * N + 3 * i + 2] = hz;

    const float4 cb = s_ctr[any ? best_j : 0];
    const float nx = __fsub_rn(hx, cb.x);
    const float ny = __fsub_rn(hy, cb.y);
    const float nz = __fsub_rn(hz, cb.z);
    const float nn = __fadd_rn(__fadd_rn(__fmul_rn(nx, nx), __fmul_rn(ny, ny)),
                               __fmul_rn(nz, nz));
    const float len = __fsqrt_rn(nn);
    out[5 * N + 3 * i + 0] = any ? __fdiv_rn(nx, len) : 0.0f;
    out[5 * N + 3 * i + 1] = any ? __fdiv_rn(ny, len) : 0.0f;
    out[5 * N + 3 * i + 2] = any ? __fdiv_rn(nz, len) : 0.0f;
}

extern "C" void kernel_launch(void* const* d_in, const int* in_sizes, int n_in,
                              void* d_out, int out_size)
{
    const float* ro = (const float*)d_in[0];   // (N,3)
    const float* rd = (const float*)d_in[1];   // (N,3)
    const float* sc = (const float*)d_in[2];   // (M,3)
    const float* sr = (const float*)d_in[3];   // (M,)

    const int n_rays = in_sizes[0] / 3;
    const int n_sph  = in_sizes[3];

    float* out = (float*)d_out;

    const int grid = (n_rays + BLOCK - 1) / BLOCK;
    raysphere_kernel<<<grid, BLOCK>>>(ro, rd, sc, sr, out, n_rays, n_sph);
}

// round 4
// speedup vs baseline: 1.2281x; 1.0278x over previous
#include <cuda_runtime.h>
#include <math_constants.h>

// Outputs packed float32, reference return order:
//   [0,    N)   t_hit
//   [N,   2N)   sphere_idx (as float, -1 for miss)
//   [2N,  5N)   hit_points  (N,3)
//   [5N,  8N)   hit_normals (N,3)
//
// Decision arithmetic bit-replicates the reference fp32 op sequence in the
// half-b domain (power-of-two scalings commute exactly with rn rounding,
// sqrt, div). Inner loop: 2 spheres/lane via packed f32x2 ops, shared data
// pre-packed as ulonglong2 so LDS.128 lands operands in aligned u64 pairs
// with zero repacking MOVs; hit test is an integer sign-bit test on the
// packed q (no unpack on the fast path).

#define MAX_SPH  256
#define MAX_PAIR (MAX_SPH / 2)
#define BLOCK    256

typedef unsigned long long u64;

__device__ __forceinline__ u64 mul2(u64 a, u64 b) {
    u64 d; asm("mul.rn.f32x2 %0, %1, %2;" : "=l"(d) : "l"(a), "l"(b)); return d;
}
__device__ __forceinline__ u64 add2(u64 a, u64 b) {
    u64 d; asm("add.rn.f32x2 %0, %1, %2;" : "=l"(d) : "l"(a), "l"(b)); return d;
}
__device__ __forceinline__ u64 fma2(u64 a, u64 b, u64 c) {
    u64 d; asm("fma.rn.f32x2 %0, %1, %2, %3;" : "=l"(d) : "l"(a), "l"(b), "l"(c)); return d;
}
__device__ __forceinline__ u64 pkf(float lo, float hi) {
    return (u64)__float_as_uint(lo) | ((u64)__float_as_uint(hi) << 32);
}
__device__ __forceinline__ float lo_f(u64 v) { return __int_as_float((int)(unsigned)v); }
__device__ __forceinline__ float hi_f(u64 v) { return __int_as_float((int)(v >> 32)); }

__global__ __launch_bounds__(BLOCK)
void raysphere_kernel(const float* __restrict__ ro,
                      const float* __restrict__ rd,
                      const float* __restrict__ sc,
                      const float* __restrict__ sr,
                      float* __restrict__ out,
                      int n_rays, int n_sph)
{
    // Pre-packed pair data: sXY[k] = {pack(x0,x1), pack(y0,y1)},
    //                       sZW[k] = {pack(z0,z1), pack(w0,w1)}, w = |c|^2 - r^2
    __shared__ ulonglong2 sXY[MAX_PAIR];
    __shared__ ulonglong2 sZW[MAX_PAIR];
    __shared__ float4     s_ctr[MAX_SPH];   // for the normal gather + odd tail

    const int tid    = threadIdx.x;
    const int n_pair = n_sph >> 1;

    for (int j = tid; j < n_sph; j += BLOCK) {
        float cx = sc[3 * j + 0];
        float cy = sc[3 * j + 1];
        float cz = sc[3 * j + 2];
        float r  = sr[j];
        float s2 = __fadd_rn(__fadd_rn(__fmul_rn(cx, cx), __fmul_rn(cy, cy)),
                             __fmul_rn(cz, cz));
        float w  = __fsub_rn(s2, __fmul_rn(r, r));
        s_ctr[j] = make_float4(cx, cy, cz, w);
    }
    __syncthreads();
    for (int k = tid; k < n_pair; k += BLOCK) {
        float4 p0 = s_ctr[2 * k], p1 = s_ctr[2 * k + 1];
        sXY[k] = make_ulonglong2(pkf(p0.x, p1.x), pkf(p0.y, p1.y));
        sZW[k] = make_ulonglong2(pkf(p0.z, p1.z), pkf(p0.w, p1.w));
    }
    __syncthreads();

    const int i = blockIdx.x * BLOCK + tid;
    if (i >= n_rays) return;

    const float ox = ro[3 * i + 0];
    const float oy = ro[3 * i + 1];
    const float oz = ro[3 * i + 2];
    const float dx = rd[3 * i + 0];
    const float dy = rd[3 * i + 1];
    const float dz = rd[3 * i + 2];

    // jnp.sum(v*v): rounded squares, left-to-right add (reference order)
    const float a   = __fadd_rn(__fadd_rn(__fmul_rn(dx, dx), __fmul_rn(dy, dy)),
                                __fmul_rn(dz, dz));
    const float ddo = __fadd_rn(__fadd_rn(__fmul_rn(dx, ox), __fmul_rn(dy, oy)),
                                __fmul_rn(dz, oz));
    const float on2 = __fadd_rn(__fadd_rn(__fmul_rn(ox, ox), __fmul_rn(oy, oy)),
                                __fmul_rn(oz, oz));

    // Packed broadcast ray constants; dot chains computed NEGATED (exact flips)
    const u64 pndx = pkf(-dx, -dx), pndy = pkf(-dy, -dy), pndz = pkf(-dz, -dz);
    const u64 pnox = pkf(-ox, -ox), pnoy = pkf(-oy, -oy), pnoz = pkf(-oz, -oz);
    const u64 pddo = pkf(ddo, ddo);
    const u64 pon2 = pkf(on2, on2);
    const u64 pna  = pkf(-a, -a);

    float best_m = CUDART_INF_F;   // half-b numerator reject bound
    float best_t = CUDART_INF_F;   // reference-exact t
    int   best_j = 0;

    #pragma unroll 8
    for (int k = 0; k < n_pair; k++) {
        const ulonglong2 A = sXY[k];      // A.x={x0,x1}  A.y={y0,y1}
        const ulonglong2 B = sZW[k];      // B.x={z0,z1}  B.y={w0,w1}

        // -ddc, -odc : exact negations of reference fma chains (k = 0 -> 2)
        const u64 nddc = fma2(pndz, B.x, fma2(pndy, A.y, mul2(pndx, A.x)));
        const u64 nodc = fma2(pnoz, B.x, fma2(pnoy, A.y, mul2(pnox, A.x)));

        const u64 x2  = add2(pddo, nddc);            //  ddo - ddc   (= b/2)
        const u64 m2o = add2(nodc, nodc);            //  -2*odc (exact)
        const u64 c2  = add2(add2(pon2, m2o), B.y);  //  (on2 - 2odc) + cconst
        const u64 q2  = add2(mul2(x2, x2), mul2(pna, c2));   // disc/4 per lane

        // "any lane >= 0" == NOT(both sign bits set). (-0.0f cannot occur:
        // rn add of +0 and -0 is +0, so sign-bit <=> q < 0.)
        const int qlo_i = (int)(unsigned)q2;
        const int qhi_i = (int)(q2 >> 32);
        if ((qlo_i & qhi_i) >= 0) {                  // rare tail
            const float qlo = __int_as_float(qlo_i);
            const float qhi = __int_as_float(qhi_i);
            if (qlo >= 0.0f) {
                const float x  = lo_f(x2);
                const float sq = __fsqrt_rn(qlo);    // = sqrt_disc/2 exactly
                const float m1 = __fsub_rn(-x, sq);
                const float m0 = __fadd_rn(-x, sq);
                const float m  = (m1 > 0.0f) ? m1 : m0;
                if (m > 0.0f && m < best_m) {
                    best_m = m;
                    const float t = __fdiv_rn(m, a); // == num/(2a) exactly
                    if (t < best_t) { best_t = t; best_j = 2 * k; }
                }
            }
            if (qhi >= 0.0f) {
                const float x  = hi_f(x2);
                const float sq = __fsqrt_rn(qhi);
                const float m1 = __fsub_rn(-x, sq);
                const float m0 = __fadd_rn(-x, sq);
                const float m  = (m1 > 0.0f) ? m1 : m0;
                if (m > 0.0f && m < best_m) {
                    best_m = m;
                    const float t = __fdiv_rn(m, a);
                    if (t < best_t) { best_t = t; best_j = 2 * k + 1; }
                }
            }
        }
    }

    // Scalar remainder if n_sph is odd (not hit for 256)
    for (int j = 2 * n_pair; j < n_sph; j++) {
        const float4 s = s_ctr[j];
        const float ddc = __fmaf_rn(dz, s.z, __fmaf_rn(dy, s.y, __fmul_rn(dx, s.x)));
        const float odc = __fmaf_rn(oz, s.z, __fmaf_rn(oy, s.y, __fmul_rn(ox, s.x)));
        const float x   = __fsub_rn(ddo, ddc);
        const float c   = __fadd_rn(__fsub_rn(on2, __fmul_rn(2.0f, odc)), s.w);
        const float q   = __fsub_rn(__fmul_rn(x, x), __fmul_rn(a, c));
        if (q >= 0.0f) {
            const float sq = __fsqrt_rn(q);
            const float m1 = __fsub_rn(-x, sq);
            const float m0 = __fadd_rn(-x, sq);
            const float m  = (m1 > 0.0f) ? m1 : m0;
            if (m > 0.0f && m < best_m) {
                best_m = m;
                const float t = __fdiv_rn(m, a);
                if (t < best_t) { best_t = t; best_j = j; }
            }
        }
    }

    const float t_hit = best_t;
    const bool  any   = isfinite(t_hit);

    const long long N = n_rays;
    out[i]     = t_hit;
    out[N + i] = any ? (float)best_j : -1.0f;

    // hit_points = o + t*d (mul then add — matches reference)
    const float hx = __fadd_rn(ox, __fmul_rn(t_hit, dx));
    const float hy = __fadd_rn(oy, __fmul_rn(t_hit, dy));
    const float hz = __fadd_rn(oz, __fmul_rn(t_hit, dz));
    out[2 * N + 3 * i + 0] = hx;
    out[2 * N + 3 * i + 1] = hy;
    out[2 * N + 3 * i + 2] = hz;

    const float4 cb = s_ctr[any ? best_j : 0];
    const float nx = __fsub_rn(hx, cb.x);
    const float ny = __fsub_rn(hy, cb.y);
    const float nz = __fsub_rn(hz, cb.z);
    const float nn = __fadd_rn(__fadd_rn(__fmul_rn(nx, nx), __fmul_rn(ny, ny)),
                               __fmul_rn(nz, nz));
    const float len = __fsqrt_rn(nn);
    out[5 * N + 3 * i + 0] = any ? __fdiv_rn(nx, len) : 0.0f;
    out[5 * N + 3 * i + 1] = any ? __fdiv_rn(ny, len) : 0.0f;
    out[5 * N + 3 * i + 2] = any ? __fdiv_rn(nz, len) : 0.0f;
}

extern "C" void kernel_launch(void* const* d_in, const int* in_sizes, int n_in,
                              void* d_out, int out_size)
{
    const float* ro = (const float*)d_in[0];   // (N,3)
    const float* rd = (const float*)d_in[1];   // (N,3)
    const float* sc = (const float*)d_in[2];   // (M,3)
    const float* sr = (const float*)d_in[3];   // (M,)

    const int n_rays = in_sizes[0] / 3;
    const int n_sph  = in_sizes[3];

    float* out = (float*)d_out;

    const int grid = (n_rays + BLOCK - 1) / BLOCK;
    raysphere_kernel<<<grid, BLOCK>>>(ro, rd, sc, sr, out, n_rays, n_sph);
}